// round 4
// baseline (speedup 1.0000x reference)
#include <cuda_runtime.h>
#include <cuda_bf16.h>
#include <mma.h>

using namespace nvcuda;

#define T_ROWS    8192
#define K_DIM     4096
#define N_NODES   63
#define N_PAD     64
#define DEPTH_    6
#define N_LEAVES  64
#define NB_CLS    10

#define MT        64            // rows per block
#define KC        64            // k elements per chunk
#define LD        72            // smem leading dim (bf16 elems / fp32 elems)
#define NTHREADS  512           // 16 warps = 2 k-groups x 8 warps
#define NBLOCKS   (T_ROWS / MT) // 128
#define NCHUNK    (K_DIM / KC)  // 64
#define CPG       (NCHUNK / 2)  // 32 chunks per k-group

// dynamic smem layout (per k-group: [2][MT][LD] bf16 X + [2][N_PAD][LD] bf16 W)
#define XBUF_B    (MT * LD * 2)          // 9216 bytes per X buffer
#define GROUP_B   (4 * XBUF_B)           // 36864 bytes per group
#define SMEM_B    (2 * GROUP_B)          // 73728 bytes total
#define ACC_B     (MT * LD * 4)          // 18432 bytes per fp32 acc region (aliased)

__device__ float g_partial[NBLOCKS];
__device__ int   g_ticket;

__global__ void __launch_bounds__(NTHREADS, 1) sdt_main(
    const float* __restrict__ X, const float* __restrict__ W,
    const float* __restrict__ bias, const float* __restrict__ beta,
    const float* __restrict__ leaf_dist, const float* __restrict__ cls_r,
    float* __restrict__ out)
{
    extern __shared__ __align__(16) unsigned char dynsm[];
    __shared__ float leaf_r[N_LEAVES];
    __shared__ float red_s[NTHREADS / 32];
    __shared__ int   is_last_s;

    const int tid  = threadIdx.x;
    const int wid  = tid >> 5;
    const int lane = tid & 31;
    const int grp  = wid >> 3;          // k-group 0/1
    const int gtid = tid & 255;         // tid within group
    const int r0   = gtid >> 4;         // 0..15 base row for loads
    const int c4   = gtid & 15;         // float4 column within chunk
    const long mrow0 = (long)blockIdx.x * MT;

    unsigned char* gbase = dynsm + grp * GROUP_B;
    __nv_bfloat16 (*Xs)[MT][LD]    = reinterpret_cast<__nv_bfloat16 (*)[MT][LD]>(gbase);
    __nv_bfloat16 (*Ws)[N_PAD][LD] = reinterpret_cast<__nv_bfloat16 (*)[N_PAD][LD]>(gbase + 2 * XBUF_B);

    // per-leaf expected reward (done by warps 0-1 while others start loading)
    if (tid < N_LEAVES) {
        const float* ldp = leaf_dist + tid * NB_CLS;
        float mx = ldp[0];
        #pragma unroll
        for (int c = 1; c < NB_CLS; c++) mx = fmaxf(mx, ldp[c]);
        float se = 0.f, sr = 0.f;
        #pragma unroll
        for (int c = 0; c < NB_CLS; c++) {
            float e = __expf(ldp[c] - mx);
            se += e; sr += e * cls_r[c];
        }
        leaf_r[tid] = sr / se;
    }

    float4 xr[4], wr[4];
    auto load_regs = [&](int cg) {
        #pragma unroll
        for (int i = 0; i < 4; i++) {
            int row = r0 + 16 * i;
            xr[i] = *reinterpret_cast<const float4*>(&X[(mrow0 + row) * K_DIM + (long)cg * KC + c4 * 4]);
            if (row < N_NODES)
                wr[i] = *reinterpret_cast<const float4*>(&W[(long)row * K_DIM + (long)cg * KC + c4 * 4]);
            else
                wr[i] = make_float4(0.f, 0.f, 0.f, 0.f);
        }
    };
    auto store_smem = [&](int buf) {
        #pragma unroll
        for (int i = 0; i < 4; i++) {
            int row = r0 + 16 * i;
            __nv_bfloat162* px = reinterpret_cast<__nv_bfloat162*>(&Xs[buf][row][c4 * 4]);
            px[0] = __floats2bfloat162_rn(xr[i].x, xr[i].y);
            px[1] = __floats2bfloat162_rn(xr[i].z, xr[i].w);
            __nv_bfloat162* pw = reinterpret_cast<__nv_bfloat162*>(&Ws[buf][row][c4 * 4]);
            pw[0] = __floats2bfloat162_rn(wr[i].x, wr[i].y);
            pw[1] = __floats2bfloat162_rn(wr[i].z, wr[i].w);
        }
    };
    // per-group barrier (256 threads each, ids 1 and 2) — groups run independently
    auto gbar = [&]() {
        asm volatile("bar.sync %0, %1;" :: "r"(grp + 1), "r"(256) : "memory");
    };

    // 8 warps per group cover the 64x64 output: mtile = wid8&3, nbase = (wid8>>2)*2
    const int wid8  = wid & 7;
    const int mtile = wid8 & 3;
    const int nbase = (wid8 >> 2) * 2;

    wmma::fragment<wmma::accumulator, 16, 16, 16, float> acc0, acc1;
    wmma::fill_fragment(acc0, 0.f);
    wmma::fill_fragment(acc1, 0.f);

    const int c0 = grp * CPG;           // this group's first chunk
    load_regs(c0);
    store_smem(0);
    gbar();

    for (int c = 0; c < CPG; c++) {
        int buf = c & 1;
        if (c + 1 < CPG) load_regs(c0 + c + 1);     // prefetch next chunk
        #pragma unroll
        for (int ks = 0; ks < KC / 16; ks++) {
            wmma::fragment<wmma::matrix_a, 16, 16, 16, __nv_bfloat16, wmma::row_major> fa;
            wmma::load_matrix_sync(fa, &Xs[buf][mtile * 16][ks * 16], LD);
            wmma::fragment<wmma::matrix_b, 16, 16, 16, __nv_bfloat16, wmma::col_major> fb0, fb1;
            wmma::load_matrix_sync(fb0, &Ws[buf][nbase * 16][ks * 16], LD);
            wmma::load_matrix_sync(fb1, &Ws[buf][(nbase + 1) * 16][ks * 16], LD);
            wmma::mma_sync(acc0, fa, fb0, acc0);
            wmma::mma_sync(acc1, fa, fb1, acc1);
        }
        if (c + 1 < CPG) store_smem(buf ^ 1);       // prev readers of buf^1 done before last gbar
        gbar();
    }

    // both groups done -> dump accumulators into two aliased fp32 regions
    __syncthreads();
    float (*accA)[LD] = reinterpret_cast<float (*)[LD]>(dynsm);
    float (*accB)[LD] = reinterpret_cast<float (*)[LD]>(dynsm + ACC_B);
    float (*accG)[LD] = grp ? accB : accA;
    wmma::store_matrix_sync(&accG[mtile * 16][nbase * 16],       acc0, LD, wmma::mem_row_major);
    wmma::store_matrix_sync(&accG[mtile * 16][(nbase + 1) * 16], acc1, LD, wmma::mem_row_major);
    __syncthreads();

    // epilogue: one thread per row, bottom-up tree collapse
    float rowval = 0.f;
    if (tid < MT) {
        float v[N_LEAVES];
        #pragma unroll
        for (int j = 0; j < N_LEAVES; j++) v[j] = leaf_r[j];
        #pragma unroll
        for (int lvl = DEPTH_ - 1; lvl >= 0; lvl--) {
            int base = (1 << lvl) - 1;
            #pragma unroll
            for (int i = 0; i < (1 << lvl); i++) {
                int n = base + i;
                float z = accA[tid][n] + accB[tid][n];   // combine split-K halves
                float a = beta[n] * (z + bias[n]);
                float p = 1.f / (1.f + __expf(-a));
                v[i] = p * v[2 * i] + (1.f - p) * v[2 * i + 1];
            }
        }
        rowval = v[0];
    }

    // deterministic in-block reduction
    #pragma unroll
    for (int o = 16; o > 0; o >>= 1) rowval += __shfl_down_sync(0xffffffffu, rowval, o);
    if (lane == 0) red_s[wid] = rowval;
    __syncthreads();
    if (tid == 0) {
        float s = 0.f;
        #pragma unroll
        for (int i = 0; i < NTHREADS / 32; i++) s += red_s[i];
        g_partial[blockIdx.x] = s;
        __threadfence();
        int t = atomicAdd(&g_ticket, 1);
        is_last_s = (t == NBLOCKS - 1) ? 1 : 0;
    }
    __syncthreads();

    // last-arriving block: fixed-order final sum (deterministic), reset ticket
    if (is_last_s) {
        if (wid == 0) {
            __threadfence();
            float v = 0.f;
            #pragma unroll
            for (int i = 0; i < NBLOCKS / 32; i++)    // fixed order per lane
                v += g_partial[lane + 32 * i];
            #pragma unroll
            for (int o = 16; o > 0; o >>= 1) v += __shfl_down_sync(0xffffffffu, v, o);
            if (lane == 0) {
                out[0] = v;
                g_ticket = 0;                          // reset for next replay
            }
        }
    }
}

extern "C" void kernel_launch(void* const* d_in, const int* in_sizes, int n_in,
                              void* d_out, int out_size) {
    const float* X         = (const float*)d_in[0];
    const float* W         = (const float*)d_in[1];
    const float* b         = (const float*)d_in[2];
    const float* beta      = (const float*)d_in[3];
    const float* leaf_dist = (const float*)d_in[4];
    const float* cls_r     = (const float*)d_in[5];

    cudaFuncSetAttribute(sdt_main, cudaFuncAttributeMaxDynamicSharedMemorySize, SMEM_B);
    sdt_main<<<NBLOCKS, NTHREADS, SMEM_B>>>(X, W, b, beta, leaf_dist, cls_r, (float*)d_out);
}

// round 7
// speedup vs baseline: 1.0828x; 1.0828x over previous
#include <cuda_runtime.h>
#include <cuda_bf16.h>
#include <mma.h>
#include <cstdint>

using namespace nvcuda;

#define T_ROWS    8192
#define K_DIM     4096
#define N_NODES   63
#define DEPTH_    6
#define N_LEAVES  64
#define NB_CLS    10

#define MT        64                   // rows per CTA
#define KC        64                   // k elems per chunk
#define NCHUNK    (K_DIM / KC)         // 64
#define NSTAGE    4                    // ring depth
#define LD        72                   // smem leading dim (bf16 elems); 144B rows
#define NT        256                  // 4 consumer + 4 producer warps
#define NBLOCKS   (T_ROWS / MT)        // 128

#define XTILE_B   (MT * LD * 2)        // 9216 B
#define STAGE_B   (2 * XTILE_B)        // X + W = 18432 B
#define DYN_B     (NSTAGE * STAGE_B)   // 73728 B

__device__ float g_partial[NBLOCKS];
__device__ int   g_ticket;

static __device__ __forceinline__ uint32_t smem_u32(const void* p) {
    uint32_t a;
    asm("{ .reg .u64 t; cvta.to.shared.u64 t, %1; cvt.u32.u64 %0, t; }" : "=r"(a) : "l"(p));
    return a;
}
static __device__ __forceinline__ void mbar_init(uint32_t a, uint32_t cnt) {
    asm volatile("mbarrier.init.shared.b64 [%0], %1;" :: "r"(a), "r"(cnt) : "memory");
}
static __device__ __forceinline__ void mbar_arrive(uint32_t a) {
    asm volatile("mbarrier.arrive.shared.b64 _, [%0];" :: "r"(a) : "memory");
}
static __device__ __forceinline__ void wait_parity(uint32_t mbar, uint32_t phase) {
    uint32_t done;
    asm volatile(
        "{\n\t.reg .pred p;\n\t"
        "mbarrier.try_wait.parity.acquire.cta.shared::cta.b64 p, [%1], %2;\n\t"
        "selp.b32 %0, 1, 0, p;\n\t}"
        : "=r"(done) : "r"(mbar), "r"(phase) : "memory");
    if (!done) {
        asm volatile(
            "{\n\t.reg .pred P1;\n\t"
            "W0_%=:\n\t"
            "mbarrier.try_wait.parity.acquire.cta.shared::cta.b64 P1, [%0], %1, 0x989680;\n\t"
            "@P1 bra.uni W1_%=;\n\t"
            "bra.uni W0_%=;\n\t"
            "W1_%=:\n\t}"
            :: "r"(mbar), "r"(phase) : "memory");
    }
}
static __device__ __forceinline__ void sts128(uint32_t a, uint4 v) {
    asm volatile("st.shared.v4.b32 [%0], {%1,%2,%3,%4};"
                 :: "r"(a), "r"(v.x), "r"(v.y), "r"(v.z), "r"(v.w) : "memory");
}
static __device__ __forceinline__ uint4 pack8(float4 a, float4 b) {
    uint4 u; __nv_bfloat162 h;
    h = __floats2bfloat162_rn(a.x, a.y); u.x = *reinterpret_cast<uint32_t*>(&h);
    h = __floats2bfloat162_rn(a.z, a.w); u.y = *reinterpret_cast<uint32_t*>(&h);
    h = __floats2bfloat162_rn(b.x, b.y); u.z = *reinterpret_cast<uint32_t*>(&h);
    h = __floats2bfloat162_rn(b.z, b.w); u.w = *reinterpret_cast<uint32_t*>(&h);
    return u;
}

__global__ void __launch_bounds__(NT, 1) sdt_main(
    const float* __restrict__ X, const float* __restrict__ W,
    const float* __restrict__ bias, const float* __restrict__ beta,
    const float* __restrict__ leaf_dist, const float* __restrict__ cls_r,
    float* __restrict__ out)
{
    extern __shared__ __align__(128) unsigned char dynsm[];
    __shared__ __align__(8) unsigned long long full_mb[NSTAGE], empty_mb[NSTAGE];
    __shared__ float leaf_r[N_LEAVES];
    __shared__ float bias_s[N_NODES], beta_s[N_NODES];
    __shared__ float red_s[NT / 32];
    __shared__ int   is_last_s;

    const int tid  = threadIdx.x;
    const int wid  = tid >> 5;
    const int lane = tid & 31;
    const uint32_t dbase = smem_u32(dynsm);
    const long mrow0 = (long)blockIdx.x * MT;

    if (tid < NSTAGE) {
        mbar_init(smem_u32(&full_mb[tid]),  4);   // 4 producer warps arrive
        mbar_init(smem_u32(&empty_mb[tid]), 4);   // 4 consumer warps arrive
    }
    if (tid < N_NODES) { bias_s[tid] = bias[tid]; beta_s[tid] = beta[tid]; }
    if (tid < N_LEAVES) {
        const float* ldp = leaf_dist + tid * NB_CLS;
        float mx = ldp[0];
        #pragma unroll
        for (int c = 1; c < NB_CLS; c++) mx = fmaxf(mx, ldp[c]);
        float se = 0.f, sr = 0.f;
        #pragma unroll
        for (int c = 0; c < NB_CLS; c++) {
            float e = __expf(ldp[c] - mx);
            se += e; sr += e * cls_r[c];
        }
        leaf_r[tid] = sr / se;
    }
    __syncthreads();

    wmma::fragment<wmma::accumulator, 16, 16, 16, float> acc[2][2];

    if (wid >= 4) {
        // ================= PRODUCER (warps 4-7, 128 threads) =================
        const int pt    = tid - 128;          // 0..127
        const int c8    = pt & 7;             // 16B column within 128B bf16 row
        const int rbase = pt >> 3;            // 0..15
        const float* Xg = X + mrow0 * K_DIM;

        float4 st[16];
        auto ldchunk = [&](int i) {
            #pragma unroll
            for (int jj = 0; jj < 4; jj++) {
                const float4* p = reinterpret_cast<const float4*>(
                    Xg + (long)(rbase + 16 * jj) * K_DIM + i * KC + c8 * 8);
                st[2 * jj] = p[0]; st[2 * jj + 1] = p[1];
            }
            #pragma unroll
            for (int jj = 0; jj < 4; jj++) {
                int r = rbase + 16 * jj;
                if (r < N_NODES) {
                    const float4* p = reinterpret_cast<const float4*>(
                        W + (long)r * K_DIM + i * KC + c8 * 8);
                    st[8 + 2 * jj] = p[0]; st[9 + 2 * jj] = p[1];
                } else {
                    st[8 + 2 * jj] = make_float4(0.f, 0.f, 0.f, 0.f);
                    st[9 + 2 * jj] = st[8 + 2 * jj];
                }
            }
        };
        auto stchunk = [&](int s) {
            uint32_t base = dbase + s * STAGE_B;
            #pragma unroll
            for (int jj = 0; jj < 4; jj++)
                sts128(base + (rbase + 16 * jj) * (LD * 2) + c8 * 16,
                       pack8(st[2 * jj], st[2 * jj + 1]));
            #pragma unroll
            for (int jj = 0; jj < 4; jj++)
                sts128(base + XTILE_B + (rbase + 16 * jj) * (LD * 2) + c8 * 16,
                       pack8(st[8 + 2 * jj], st[9 + 2 * jj]));
        };

        ldchunk(0);
        for (int i = 0; i < NCHUNK; i++) {
            const int s = i & (NSTAGE - 1);
            const int w = i >> 2;
            if (w > 0) wait_parity(smem_u32(&empty_mb[s]), (w - 1) & 1);
            stchunk(s);
            __syncwarp();
            if (lane == 0) mbar_arrive(smem_u32(&full_mb[s]));
            if (i + 1 < NCHUNK) ldchunk(i + 1);   // prefetch: LDGs in flight during next wait
        }
    } else {
        // ================= CONSUMER (warps 0-3) =================
        const int mb = (wid & 1) * 32;
        const int nb = (wid >> 1) * 32;
        #pragma unroll
        for (int a = 0; a < 2; a++)
            #pragma unroll
            for (int b = 0; b < 2; b++)
                wmma::fill_fragment(acc[a][b], 0.f);

        for (int i = 0; i < NCHUNK; i++) {
            const int s = i & (NSTAGE - 1);
            wait_parity(smem_u32(&full_mb[s]), (i >> 2) & 1);
            const __nv_bfloat16* Xs = reinterpret_cast<const __nv_bfloat16*>(dynsm + s * STAGE_B);
            const __nv_bfloat16* Ws = reinterpret_cast<const __nv_bfloat16*>(dynsm + s * STAGE_B + XTILE_B);
            #pragma unroll
            for (int ks = 0; ks < KC / 16; ks++) {
                wmma::fragment<wmma::matrix_a, 16, 16, 16, __nv_bfloat16, wmma::row_major> fa0, fa1;
                wmma::fragment<wmma::matrix_b, 16, 16, 16, __nv_bfloat16, wmma::col_major> fb0, fb1;
                wmma::load_matrix_sync(fa0, Xs + (mb)      * LD + ks * 16, LD);
                wmma::load_matrix_sync(fa1, Xs + (mb + 16) * LD + ks * 16, LD);
                wmma::load_matrix_sync(fb0, Ws + (nb)      * LD + ks * 16, LD);
                wmma::load_matrix_sync(fb1, Ws + (nb + 16) * LD + ks * 16, LD);
                wmma::mma_sync(acc[0][0], fa0, fb0, acc[0][0]);
                wmma::mma_sync(acc[0][1], fa0, fb1, acc[0][1]);
                wmma::mma_sync(acc[1][0], fa1, fb0, acc[1][0]);
                wmma::mma_sync(acc[1][1], fa1, fb1, acc[1][1]);
            }
            __syncwarp();
            if (lane == 0) mbar_arrive(smem_u32(&empty_mb[s]));
        }
    }

    // ---- epilogue: dump accs into stage-0 region (all ring traffic done) ----
    __syncthreads();
    float* accS = reinterpret_cast<float*>(dynsm);
    if (wid < 4) {
        const int mb = (wid & 1) * 32;
        const int nb = (wid >> 1) * 32;
        #pragma unroll
        for (int a = 0; a < 2; a++)
            #pragma unroll
            for (int b = 0; b < 2; b++)
                wmma::store_matrix_sync(accS + (mb + 16 * a) * LD + nb + 16 * b,
                                        acc[a][b], LD, wmma::mem_row_major);
    }
    __syncthreads();

    float rowval = 0.f;
    if (tid < MT) {
        float v[N_LEAVES];
        #pragma unroll
        for (int j = 0; j < N_LEAVES; j++) v[j] = leaf_r[j];
        #pragma unroll
        for (int lvl = DEPTH_ - 1; lvl >= 0; lvl--) {
            int base = (1 << lvl) - 1;
            #pragma unroll
            for (int i = 0; i < (1 << lvl); i++) {
                int n = base + i;
                float z = accS[tid * LD + n];
                float a = beta_s[n] * (z + bias_s[n]);
                float p = 1.f / (1.f + __expf(-a));
                v[i] = p * v[2 * i] + (1.f - p) * v[2 * i + 1];
            }
        }
        rowval = v[0];
    }

    #pragma unroll
    for (int o = 16; o > 0; o >>= 1) rowval += __shfl_down_sync(0xffffffffu, rowval, o);
    if (lane == 0) red_s[wid] = rowval;
    __syncthreads();
    if (tid == 0) {
        float s = 0.f;
        #pragma unroll
        for (int i = 0; i < NT / 32; i++) s += red_s[i];
        g_partial[blockIdx.x] = s;
        __threadfence();
        int t = atomicAdd(&g_ticket, 1);
        is_last_s = (t == NBLOCKS - 1) ? 1 : 0;
    }
    __syncthreads();

    if (is_last_s && wid == 0) {
        __threadfence();
        float v = g_partial[lane] + g_partial[lane + 32] +
                  g_partial[lane + 64] + g_partial[lane + 96];
        #pragma unroll
        for (int o = 16; o > 0; o >>= 1) v += __shfl_down_sync(0xffffffffu, v, o);
        if (lane == 0) { out[0] = v; g_ticket = 0; }
    }
}

extern "C" void kernel_launch(void* const* d_in, const int* in_sizes, int n_in,
                              void* d_out, int out_size) {
    const float* X         = (const float*)d_in[0];
    const float* W         = (const float*)d_in[1];
    const float* b         = (const float*)d_in[2];
    const float* beta      = (const float*)d_in[3];
    const float* leaf_dist = (const float*)d_in[4];
    const float* cls_r     = (const float*)d_in[5];

    cudaFuncSetAttribute(sdt_main, cudaFuncAttributeMaxDynamicSharedMemorySize, DYN_B);
    sdt_main<<<NBLOCKS, NT, DYN_B>>>(X, W, b, beta, leaf_dist, cls_r, (float*)d_out);
}